// round 5
// baseline (speedup 1.0000x reference)
#include <cuda_runtime.h>
#include <cuda_bf16.h>
#include <cstdint>

#define IN_DIM    200
#define OUT_DIMX  2000
#define BATCHN    512
#define OUT_CH    32
#define KERN      9
#define L_OUTN    1992
#define FC_LENN   (OUT_CH * L_OUTN)     // 63744
#define NUM_ENTSN 100000
#define EPSV      1e-5f
#define ZSPLIT    83
#define ZCHUNK    768
#define KPAD2     224

// ---------------- device scratch ----------------
__device__ __align__(128) float g_eWT[OUT_DIMX * IN_DIM];
__device__ __align__(128) float g_x0 [BATCHN * IN_DIM];
__device__ __align__(128) float g_xa [BATCHN * OUT_DIMX];
__device__ __align__(128) __nv_bfloat16 g_cbf[(size_t)BATCHN * FC_LENN];
__device__ __align__(128) float g_Pf [(size_t)ZSPLIT * BATCHN * IN_DIM];
__device__ __align__(128) float g_y  [BATCHN * IN_DIM];
__device__ __align__(128) __nv_bfloat16 g_zbf[BATCHN * KPAD2];
__device__ float g_s1[OUT_CH * BATCHN];
__device__ float g_s2[OUT_CH * BATCHN];
__device__ float g_alpha[OUT_CH];
__device__ float g_betap[OUT_CH];

// ---------------- helpers ----------------
__device__ __forceinline__ uint32_t smem_u32(const void* p) {
    uint32_t a;
    asm("{ .reg .u64 t; cvta.to.shared.u64 t, %1; cvt.u32.u64 %0, t; }" : "=r"(a) : "l"(p));
    return a;
}
__device__ __forceinline__ void ldsm_x4(uint32_t* r, uint32_t addr) {
    asm volatile("ldmatrix.sync.aligned.m8n8.x4.shared.b16 {%0,%1,%2,%3}, [%4];"
                 : "=r"(r[0]), "=r"(r[1]), "=r"(r[2]), "=r"(r[3]) : "r"(addr));
}
__device__ __forceinline__ void ldsm_x2(uint32_t* r, uint32_t addr) {
    asm volatile("ldmatrix.sync.aligned.m8n8.x2.shared.b16 {%0,%1}, [%2];"
                 : "=r"(r[0]), "=r"(r[1]) : "r"(addr));
}
__device__ __forceinline__ void mma_bf16(float* c, const uint32_t* a, const uint32_t* b) {
    asm volatile("mma.sync.aligned.m16n8k16.row.col.f32.bf16.bf16.f32 "
                 "{%0,%1,%2,%3}, {%4,%5,%6,%7}, {%8,%9}, {%0,%1,%2,%3};"
                 : "+f"(c[0]), "+f"(c[1]), "+f"(c[2]), "+f"(c[3])
                 : "r"(a[0]), "r"(a[1]), "r"(a[2]), "r"(a[3]), "r"(b[0]), "r"(b[1]));
}
__device__ __forceinline__ float blockReduceSum(float v, float* s) {
    __syncthreads();
    #pragma unroll
    for (int o = 16; o; o >>= 1) v += __shfl_down_sync(0xffffffffu, v, o);
    int w = threadIdx.x >> 5, l = threadIdx.x & 31;
    if (l == 0) s[w] = v;
    __syncthreads();
    int nw = blockDim.x >> 5;
    if (w == 0) {
        float r = (l < nw) ? s[l] : 0.f;
        #pragma unroll
        for (int o = 16; o; o >>= 1) r += __shfl_down_sync(0xffffffffu, r, o);
        if (l == 0) s[0] = r;
    }
    __syncthreads();
    return s[0];
}

// ---------------- tiny prep ----------------
__global__ void k_transpose(const float* __restrict__ W) {
    int i = blockIdx.x * blockDim.x + threadIdx.x;
    if (i < IN_DIM * OUT_DIMX) {
        int k = i / OUT_DIMX, n = i - k * OUT_DIMX;
        g_eWT[n * IN_DIM + k] = W[i];
    }
}

// ---------------- gather + bn0 ----------------
__global__ void k_bn0(const float* __restrict__ E, const int* __restrict__ e1,
                      const float* __restrict__ g, const float* __restrict__ bt) {
    int f = blockIdx.x, b = threadIdx.x;
    float v = E[(size_t)e1[b] * IN_DIM + f];
    __shared__ float sr[32];
    float s1 = blockReduceSum(v, sr);
    float s2 = blockReduceSum(v * v, sr);
    float m = s1 * (1.f / BATCHN);
    float var = s2 * (1.f / BATCHN) - m * m;
    g_x0[b * IN_DIM + f] = (v - m) * rsqrtf(var + EPSV) * g[f] + bt[f];
}

// ---------------- fp32 SIMT GEMM (small GEMM1 only) ----------------
__global__ __launch_bounds__(256) void k_gemm1(
    const float* __restrict__ A, const float* __restrict__ B, float* __restrict__ C,
    int M, int N, int K)
{
    constexpr int KTg = 16;
    __shared__ float sA[KTg][132];
    __shared__ float sB[KTg][132];
    int m0 = blockIdx.x * 128, n0 = blockIdx.y * 128;
    int t = threadIdx.x;
    int tm = t >> 4, tn = t & 15;
    int lr = t >> 1, lk = (t & 1) * 8;
    float acc[8][8];
    #pragma unroll
    for (int i = 0; i < 8; i++)
        #pragma unroll
        for (int j = 0; j < 8; j++) acc[i][j] = 0.f;
    for (int kb = 0; kb < K; kb += KTg) {
        {
            int m = m0 + lr;
            const float* Ap = A + (size_t)m * K + (kb + lk);
            #pragma unroll
            for (int i = 0; i < 8; i++) {
                int kk = kb + lk + i;
                sA[lk + i][lr] = (m < M && kk < K) ? Ap[i] : 0.f;
            }
        }
        {
            int n = n0 + lr;
            const float* Bp = B + (size_t)n * K + (kb + lk);
            #pragma unroll
            for (int i = 0; i < 8; i++) {
                int kk = kb + lk + i;
                sB[lk + i][lr] = (n < N && kk < K) ? Bp[i] : 0.f;
            }
        }
        __syncthreads();
        #pragma unroll
        for (int kk = 0; kk < KTg; kk++) {
            float a[8], b[8];
            #pragma unroll
            for (int i = 0; i < 8; i++) a[i] = sA[kk][tm * 8 + i];
            #pragma unroll
            for (int i = 0; i < 8; i++) b[i] = sB[kk][tn * 8 + i];
            #pragma unroll
            for (int i = 0; i < 8; i++)
                #pragma unroll
                for (int j = 0; j < 8; j++) acc[i][j] += a[i] * b[j];
        }
        __syncthreads();
    }
    #pragma unroll
    for (int i = 0; i < 8; i++) {
        int m = m0 + tm * 8 + i;
        if (m >= M) continue;
        #pragma unroll
        for (int j = 0; j < 8; j++) {
            int n = n0 + tn * 8 + j;
            if (n < N) C[(size_t)m * N + n] = acc[i][j];
        }
    }
}

// ---------------- bn1 stats via windowed autocorrelation ----------------
__global__ __launch_bounds__(512) void k_statsA(const float* __restrict__ R,
                                                const int* __restrict__ ridx) {
    int b = blockIdx.x, t = threadIdx.x;
    __shared__ float sx[OUT_DIMX];
    __shared__ float red[16][54];
    __shared__ float TG[54];
    for (int i = t; i < OUT_DIMX; i += 512) sx[i] = g_xa[(size_t)b * OUT_DIMX + i];
    __syncthreads();
    float acc[54];
    #pragma unroll
    for (int i = 0; i < 54; i++) acc[i] = 0.f;
    for (int l = t; l < L_OUTN; l += 512) {
        float xv[KERN];
        #pragma unroll
        for (int k = 0; k < KERN; k++) xv[k] = sx[l + k];
        #pragma unroll
        for (int k = 0; k < KERN; k++) acc[k] += xv[k];
        int p = 9;
        #pragma unroll
        for (int k = 0; k < KERN; k++)
            #pragma unroll
            for (int k2 = k; k2 < KERN; k2++) acc[p++] += xv[k] * xv[k2];
    }
    #pragma unroll
    for (int i = 0; i < 54; i++) {
        float v = acc[i];
        #pragma unroll
        for (int o = 16; o; o >>= 1) v += __shfl_down_sync(0xffffffffu, v, o);
        if ((t & 31) == 0) red[t >> 5][i] = v;
    }
    __syncthreads();
    if (t < 54) {
        float s = 0.f;
        #pragma unroll
        for (int w = 0; w < 16; w++) s += red[w][t];
        TG[t] = s;
    }
    __syncthreads();
    if (t < OUT_CH) {
        const float* Rb = R + (size_t)ridx[b] * OUT_CH * KERN + t * KERN;
        float r[KERN];
        #pragma unroll
        for (int k = 0; k < KERN; k++) r[k] = Rb[k];
        float s1 = 0.f, s2 = 0.f;
        #pragma unroll
        for (int k = 0; k < KERN; k++) s1 += r[k] * TG[k];
        int p = 9;
        #pragma unroll
        for (int k = 0; k < KERN; k++)
            #pragma unroll
            for (int k2 = k; k2 < KERN; k2++) {
                float c = (k2 == k) ? 1.f : 2.f;
                s2 += c * r[k] * r[k2] * TG[p++];
            }
        g_s1[t * BATCHN + b] = s1;
        g_s2[t * BATCHN + b] = s2;
    }
}
__global__ void k_statsB(const float* __restrict__ g1, const float* __restrict__ b1) {
    int o = blockIdx.x;
    __shared__ float sr[32];
    float s1 = blockReduceSum(g_s1[o * BATCHN + threadIdx.x], sr);
    float s2 = blockReduceSum(g_s2[o * BATCHN + threadIdx.x], sr);
    if (threadIdx.x == 0) {
        float Nf = (float)BATCHN * (float)L_OUTN;
        float m = s1 / Nf;
        float var = s2 / Nf - m * m;
        float a = rsqrtf(var + EPSV) * g1[o];
        g_alpha[o] = a;
        g_betap[o] = b1[o] - m * a;
    }
}

// ---------------- conv1d + bn1-affine -> bf16 (paired stores) ----------------
__global__ __launch_bounds__(512) void k_conv(const float* __restrict__ R,
                                              const int* __restrict__ ridx) {
    int b = blockIdx.x;
    __shared__ float sx[OUT_DIMX];
    for (int i = threadIdx.x; i < OUT_DIMX; i += 512)
        sx[i] = g_xa[(size_t)b * OUT_DIMX + i];
    __syncthreads();
    const float* Rb = R + (size_t)ridx[b] * OUT_CH * KERN;
    for (int o = 0; o < OUT_CH; o++) {
        float r[KERN];
        #pragma unroll
        for (int k = 0; k < KERN; k++) r[k] = Rb[o * KERN + k];
        float al = g_alpha[o], be = g_betap[o];
        __nv_bfloat162* cp2 = (__nv_bfloat162*)(g_cbf + (size_t)b * FC_LENN + o * L_OUTN);
        for (int i = threadIdx.x; i < L_OUTN / 2; i += 512) {
            int l = 2 * i;
            float s0 = 0.f, s1 = 0.f;
            #pragma unroll
            for (int k = 0; k < KERN; k++) {
                s0 += r[k] * sx[l + k];
                s1 += r[k] * sx[l + 1 + k];
            }
            cp2[i] = __floats2bfloat162_rn(s0 * al + be, s1 * al + be);
        }
    }
}

// ---------------- double-buffered bf16 mma.sync TN GEMM ----------------
// MT=256: NT=128, warps 4x4.  MT=512: NT=64, warps 8x2.  Warp tile 64x32.
#define KT 32
#define SROW 40
template<int MT, bool SIG>
__global__ __launch_bounds__(512) void k_wmma_db(
    const __nv_bfloat16* __restrict__ A, int lda,
    const float* __restrict__ B, int ldb, int Nvalid, int Kvalid,
    float* __restrict__ C, long zStride, int ldc, int Kchunk)
{
    constexpr int NT  = (MT == 512) ? 64 : 128;
    constexpr int MW  = MT / 64;
    constexpr int SA  = MT * SROW;          // halves per A stage
    constexpr int SB  = NT * SROW;
    constexpr int STG = SA + SB;
    constexpr int AV  = (MT == 512) ? 4 : 2;
    extern __shared__ __align__(16) __nv_bfloat16 sm[];

    int t = threadIdx.x, lane = t & 31, wid = t >> 5;
    int wm = wid % MW, wn = wid / MW;
    int m0 = blockIdx.x * MT, n0 = blockIdx.y * NT;
    long k0 = (long)blockIdx.z * Kchunk;

    int ra, ca;
    if (MT == 512) { ra = t; ca = 0; } else { ra = t >> 1; ca = (t & 1) * 16; }
    const __nv_bfloat16* Ag = A + (size_t)(m0 + ra) * lda + k0 + ca;

    int rb = t >> 2, cb = (t & 3) * 8;
    bool bact = (NT == 128) || (t < 256);
    int nB = n0 + rb;
    const float* Bg = B + (size_t)nB * ldb + k0 + cb;
    bool nv = bact && (nB < Nvalid);

    uint32_t sm0 = smem_u32(sm);
    int rowA = lane & 15, colA = (lane >> 4) * 8;
    int rowB = lane & 7,  colB = ((lane >> 3) & 1) * 8;
    uint32_t uAoff[4], uBoff[4];
    #pragma unroll
    for (int mt = 0; mt < 4; mt++)
        uAoff[mt] = (uint32_t)((wm * 64 + mt * 16 + rowA) * SROW + colA) * 2u;
    #pragma unroll
    for (int nt = 0; nt < 4; nt++)
        uBoff[nt] = (uint32_t)(SA + (wn * 32 + nt * 8 + rowB) * SROW + colB) * 2u;

    float acc[4][4][4];
    #pragma unroll
    for (int i = 0; i < 4; i++)
        #pragma unroll
        for (int j = 0; j < 4; j++)
            #pragma unroll
            for (int q = 0; q < 4; q++) acc[i][j][q] = 0.f;

    const float4 zf = make_float4(0.f, 0.f, 0.f, 0.f);
    uint4 pa[AV];
    float4 pb0, pb1;
    int nk = Kchunk / KT;

    // ---- prefetch tile 0 ----
    #pragma unroll
    for (int j = 0; j < AV; j++) pa[j] = *(const uint4*)(Ag + j * 8);
    {
        bool kv = nv && (cb < Kvalid);
        pb0 = kv ? *(const float4*)Bg : zf;
        pb1 = kv ? *(const float4*)(Bg + 4) : zf;
    }
    // ---- store stage 0 ----
    {
        __nv_bfloat16* base = sm;
        #pragma unroll
        for (int j = 0; j < AV; j++) *(uint4*)(base + ra * SROW + ca + j * 8) = pa[j];
        if (bact) {
            __nv_bfloat162 h0 = __float22bfloat162_rn(make_float2(pb0.x, pb0.y));
            __nv_bfloat162 h1 = __float22bfloat162_rn(make_float2(pb0.z, pb0.w));
            __nv_bfloat162 h2 = __float22bfloat162_rn(make_float2(pb1.x, pb1.y));
            __nv_bfloat162 h3 = __float22bfloat162_rn(make_float2(pb1.z, pb1.w));
            uint4 v;
            v.x = *(uint32_t*)&h0; v.y = *(uint32_t*)&h1;
            v.z = *(uint32_t*)&h2; v.w = *(uint32_t*)&h3;
            *(uint4*)(base + SA + rb * SROW + cb) = v;
        }
    }
    __syncthreads();

    for (int i = 0; i < nk; i++) {
        int cur = i & 1;
        if (i + 1 < nk) {                    // prefetch tile i+1
            int kn = (i + 1) * KT;
            #pragma unroll
            for (int j = 0; j < AV; j++) pa[j] = *(const uint4*)(Ag + kn + j * 8);
            bool kv = nv && (kn + cb < Kvalid);
            pb0 = kv ? *(const float4*)(Bg + kn) : zf;
            pb1 = kv ? *(const float4*)(Bg + kn + 4) : zf;
        }
        // compute on stage cur
        uint32_t stB = (uint32_t)cur * STG * 2u;
        #pragma unroll
        for (int ks = 0; ks < 2; ks++) {
            uint32_t af[4][4], bf[4][2];
            #pragma unroll
            for (int mt = 0; mt < 4; mt++) ldsm_x4(af[mt], sm0 + stB + uAoff[mt] + ks * 32);
            #pragma unroll
            for (int nt = 0; nt < 4; nt++) ldsm_x2(bf[nt], sm0 + stB + uBoff[nt] + ks * 32);
            #pragma unroll
            for (int mt = 0; mt < 4; mt++)
                #pragma unroll
                for (int nt = 0; nt < 4; nt++) mma_bf16(acc[mt][nt], af[mt], bf[nt]);
        }
        if (i + 1 < nk) {                    // store prefetched to other stage
            __nv_bfloat16* base = sm + (cur ^ 1) * STG;
            #pragma unroll
            for (int j = 0; j < AV; j++) *(uint4*)(base + ra * SROW + ca + j * 8) = pa[j];
            if (bact) {
                __nv_bfloat162 h0 = __float22bfloat162_rn(make_float2(pb0.x, pb0.y));
                __nv_bfloat162 h1 = __float22bfloat162_rn(make_float2(pb0.z, pb0.w));
                __nv_bfloat162 h2 = __float22bfloat162_rn(make_float2(pb1.x, pb1.y));
                __nv_bfloat162 h3 = __float22bfloat162_rn(make_float2(pb1.z, pb1.w));
                uint4 v;
                v.x = *(uint32_t*)&h0; v.y = *(uint32_t*)&h1;
                v.z = *(uint32_t*)&h2; v.w = *(uint32_t*)&h3;
                *(uint4*)(base + SA + rb * SROW + cb) = v;
            }
        }
        __syncthreads();
    }

    // epilogue
    int gq = lane >> 2, gr = lane & 3;
    float* Cz = C + (long)blockIdx.z * zStride;
    #pragma unroll
    for (int mt = 0; mt < 4; mt++) {
        int m = m0 + wm * 64 + mt * 16 + gq;
        #pragma unroll
        for (int nt = 0; nt < 4; nt++) {
            int n = n0 + wn * 32 + nt * 8 + 2 * gr;
            if (n < Nvalid) {
                float2 v0 = make_float2(acc[mt][nt][0], acc[mt][nt][1]);
                float2 v1 = make_float2(acc[mt][nt][2], acc[mt][nt][3]);
                if (SIG) {
                    v0.x = 1.f / (1.f + __expf(-v0.x));
                    v0.y = 1.f / (1.f + __expf(-v0.y));
                    v1.x = 1.f / (1.f + __expf(-v1.x));
                    v1.y = 1.f / (1.f + __expf(-v1.y));
                }
                *(float2*)(Cz + (size_t)m * ldc + n) = v0;
                *(float2*)(Cz + (size_t)(m + 8) * ldc + n) = v1;
            }
        }
    }
}

// ---------------- split-K reduce, then bn2 + tanh (+K pad) ----------------
__global__ void k_redP() {
    int i = blockIdx.x * blockDim.x + threadIdx.x;
    if (i < BATCHN * IN_DIM) {
        float y = 0.f;
        for (int z = 0; z < ZSPLIT; z++)
            y += g_Pf[(size_t)z * BATCHN * IN_DIM + i];
        g_y[i] = y;
    }
}
__global__ void k_bn2(const float* __restrict__ g2, const float* __restrict__ b2) {
    int j = blockIdx.x, b = threadIdx.x;
    if (j >= IN_DIM) {
        g_zbf[b * KPAD2 + j] = __nv_bfloat16(0.f);
        return;
    }
    float y = g_y[b * IN_DIM + j];
    __shared__ float sr[32];
    float s1 = blockReduceSum(y, sr);
    float s2 = blockReduceSum(y * y, sr);
    float m = s1 * (1.f / BATCHN);
    float var = s2 * (1.f / BATCHN) - m * m;
    float zz = tanhf((y - m) * rsqrtf(var + EPSV) * g2[j] + b2[j]);
    g_zbf[b * KPAD2 + j] = __float2bfloat16(zz);
}

// ---------------- launcher ----------------
extern "C" void kernel_launch(void* const* d_in, const int* in_sizes, int n_in,
                              void* d_out, int out_size) {
    const float* E   = (const float*)d_in[0];
    const float* R   = (const float*)d_in[1];
    const float* eW  = (const float*)d_in[2];
    const float* fcW = (const float*)d_in[3];
    const float* g0  = (const float*)d_in[4];
    const float* b0  = (const float*)d_in[5];
    const float* g1  = (const float*)d_in[6];
    const float* b1  = (const float*)d_in[7];
    const float* g2  = (const float*)d_in[8];
    const float* b2  = (const float*)d_in[9];
    const int*   e1  = (const int*)d_in[10];
    const int*   ri  = (const int*)d_in[11];
    float* out = (float*)d_out;

    float *eWT, *x0, *xa, *Pf;
    cudaGetSymbolAddress((void**)&eWT, g_eWT);
    cudaGetSymbolAddress((void**)&x0,  g_x0);
    cudaGetSymbolAddress((void**)&xa,  g_xa);
    cudaGetSymbolAddress((void**)&Pf,  g_Pf);
    __nv_bfloat16 *cbf, *zbf;
    cudaGetSymbolAddress((void**)&cbf, g_cbf);
    cudaGetSymbolAddress((void**)&zbf, g_zbf);

    // dynamic smem: fc = 2*(256*40+128*40)*2 = 61440 B; logits = 2*(512*40+64*40)*2 = 92160 B
    cudaFuncSetAttribute(k_wmma_db<256, false>, cudaFuncAttributeMaxDynamicSharedMemorySize, 61440);
    cudaFuncSetAttribute(k_wmma_db<512, true>,  cudaFuncAttributeMaxDynamicSharedMemorySize, 92160);

    k_transpose<<<(IN_DIM * OUT_DIMX + 255) / 256, 256>>>(eW);
    k_bn0<<<IN_DIM, BATCHN>>>(E, e1, g0, b0);
    k_gemm1<<<dim3(4, 16), 256>>>(x0, eWT, xa, BATCHN, OUT_DIMX, IN_DIM);
    k_statsA<<<BATCHN, 512>>>(R, ri);
    k_statsB<<<OUT_CH, BATCHN>>>(g1, b1);
    k_conv<<<BATCHN, 512>>>(R, ri);

    // fc GEMM: 256x128 tiles, split-K 83 x 768
    k_wmma_db<256, false><<<dim3(2, 2, ZSPLIT), 512, 61440>>>(
        cbf, FC_LENN, fcW, FC_LENN, IN_DIM, ZCHUNK,
        Pf, (long)BATCHN * IN_DIM, IN_DIM, ZCHUNK);

    k_redP<<<(BATCHN * IN_DIM + 255) / 256, 256>>>();
    k_bn2<<<KPAD2, BATCHN>>>(g2, b2);

    // logits GEMM + sigmoid: 512x64 tiles — E streamed exactly once
    k_wmma_db<512, true><<<dim3(1, (NUM_ENTSN + 63) / 64, 1), 512, 92160>>>(
        zbf, KPAD2, E, IN_DIM, NUM_ENTSN, IN_DIM,
        out, 0L, NUM_ENTSN, KPAD2);

    (void)in_sizes; (void)n_in; (void)out_size;
}